// round 10
// baseline (speedup 1.0000x reference)
#include <cuda_runtime.h>
#include <math.h>
#include <float.h>

#define Nn   100000
#define Ee   1600000
#define FIN  256
#define Hh   64
#define Cc   40

#define EBLK 296        // edge-processing blocks fused into K1
#define GB1  1563       // gemm1 blocks = ceil(Nn/64)
#define SCAN_BLKS 25    // 25 * 4096 >= Nn

// ---------------- scratch (device globals) ----------------
__device__ float2 g_dc[Nn];        // {sum(ew), count} accumulated atomically
__device__ float  g_dinv[Nn];
__device__ int    g_cnt[Nn];
__device__ int    g_off[Nn];       // block-local exclusive offsets
__device__ int    g_bsum[SCAN_BLKS];
__device__ int    g_bb[SCAN_BLKS]; // exclusive block bases
__device__ int    g_cur[Nn];       // scatter cursors (memset 0)
__device__ int2   g_csr[Ee];       // interleaved {src, norm_bits}
__device__ float  g_xw[Nn * Hh];
__device__ float  g_h[Nn * Hh];
__device__ float  g_hw[Nn * Cc];
__device__ float  g_final[Nn * Cc];

// ---------------- helpers ----------------
__device__ __forceinline__ unsigned long long dup2(float x) {
    unsigned long long r;
    asm("mov.b64 %0, {%1, %1};" : "=l"(r) : "f"(x));
    return r;
}
__device__ __forceinline__ void fma2(unsigned long long& d, unsigned long long a,
                                     unsigned long long b) {
    asm("fma.rn.f32x2 %0, %1, %2, %0;" : "+l"(d) : "l"(a), "l"(b));
}
__device__ __forceinline__ float2 unpk(unsigned long long v) {
    float2 f;
    asm("mov.b64 {%0, %1}, %2;" : "=f"(f.x), "=f"(f.y) : "l"(v));
    return f;
}
__device__ __forceinline__ void red_v2(float2* addr, float a, float b) {
    asm volatile("red.global.add.v2.f32 [%0], {%1, %2};"
                 :: "l"(addr), "f"(a), "f"(b) : "memory");
}
// per-block edge-index dtype detect: int64 node ids < 1e5 -> odd words all 0
__device__ __forceinline__ int detect64(const void* ei) {
    const unsigned int* u = (const unsigned int*)ei;
    int ok = 1;
#pragma unroll
    for (int k = 0; k < 64; k++)
        if (u[2 * k + 1] != 0u) ok = 0;
    return ok;
}
__device__ __forceinline__ int ld_idx(const void* ei, int is64, long long pos) {
    return is64 ? (int)((const long long*)ei)[pos] : ((const int*)ei)[pos];
}

// ---------------- K1: fused degcnt (edge blocks) + GEMM1 ----------------
__global__ void __launch_bounds__(256) k_fused1(const float* __restrict__ x,
                                                const float* __restrict__ W1,
                                                const float* __restrict__ ew,
                                                const void* __restrict__ ei) {
    __shared__ float xs[64 * 68];
    __shared__ float Ws[64 * 64];

    if (blockIdx.x < EBLK) {
        // -------- degree + count accumulation (grid-stride over edges) --------
        __shared__ int s64;
        if (threadIdx.x == 0) s64 = detect64(ei);
        __syncthreads();
        int is64 = s64;
        for (int e = blockIdx.x * 256 + threadIdx.x; e < Ee; e += EBLK * 256) {
            int c = ld_idx(ei, is64, (long long)Ee + e);
            red_v2(&g_dc[c], ew[e], 1.0f);
        }
        return;
    }

    // -------- GEMM1: g_xw = x @ W1 --------
    int tid = threadIdx.x;
    int tx = tid & 15, ty = tid >> 4;
    int row0 = (blockIdx.x - EBLK) * 64;

    unsigned long long acc[4][2] = {};

    for (int kt = 0; kt < 4; kt++) {
#pragma unroll
        for (int i = 0; i < 4; i++) {
            int lin = tid + i * 256;
            int r = lin >> 4, kq = lin & 15;
            float4 v = make_float4(0.f, 0.f, 0.f, 0.f);
            int rg = row0 + r;
            if (rg < Nn) v = *(const float4*)&x[rg * FIN + kt * 64 + kq * 4];
            *(float4*)&xs[r * 68 + kq * 4] = v;
        }
#pragma unroll
        for (int i = 0; i < 4; i++) {
            int lin = tid + i * 256;
            int k = lin >> 4, jq = lin & 15;
            *(float4*)&Ws[k * 64 + jq * 4] =
                *(const float4*)&W1[(kt * 64 + k) * Hh + jq * 4];
        }
        __syncthreads();

#pragma unroll 8
        for (int k = 0; k < 64; k++) {
            longlong2 wv = *(const longlong2*)&Ws[k * 64 + tx * 4];
            unsigned long long b0 = (unsigned long long)wv.x;
            unsigned long long b1 = (unsigned long long)wv.y;
#pragma unroll
            for (int i = 0; i < 4; i++) {
                unsigned long long a = dup2(xs[(ty * 4 + i) * 68 + k]);
                fma2(acc[i][0], a, b0);
                fma2(acc[i][1], a, b1);
            }
        }
        __syncthreads();
    }

#pragma unroll
    for (int i = 0; i < 4; i++) {
        int rg = row0 + ty * 4 + i;
        if (rg < Nn) {
            float2 lo = unpk(acc[i][0]);
            float2 hi = unpk(acc[i][1]);
            *(float4*)&g_xw[rg * Hh + tx * 4] = make_float4(lo.x, lo.y, hi.x, hi.y);
        }
    }
}

// ---------------- scanA: per-block local scan of counts, fused dinv ----------------
__global__ void __launch_bounds__(1024) k_scanA() {
    __shared__ int wsum[32];
    int tid = threadIdx.x, lane = tid & 31, wid = tid >> 5;
    int i0 = blockIdx.x * 4096 + tid * 4;

    int c[4];
    int s = 0;
#pragma unroll
    for (int j = 0; j < 4; j++) {
        int i = i0 + j;
        if (i < Nn) {
            float2 dc = g_dc[i];
            g_dinv[i] = rsqrtf(1.0f + dc.x);
            c[j] = (int)(dc.y + 0.5f);
            g_cnt[i] = c[j];
        } else c[j] = 0;
        s += c[j];
    }
    int x = s;
#pragma unroll
    for (int o = 1; o < 32; o <<= 1) {
        int t = __shfl_up_sync(0xffffffffu, x, o);
        if (lane >= o) x += t;
    }
    if (lane == 31) wsum[wid] = x;
    __syncthreads();
    if (wid == 0) {
        int y = wsum[lane];
#pragma unroll
        for (int o = 1; o < 32; o <<= 1) {
            int t = __shfl_up_sync(0xffffffffu, y, o);
            if (lane >= o) y += t;
        }
        wsum[lane] = y;
    }
    __syncthreads();
    int run = (x - s) + (wid ? wsum[wid - 1] : 0);  // exclusive
#pragma unroll
    for (int j = 0; j < 4; j++) {
        if (i0 + j < Nn) g_off[i0 + j] = run;
        run += c[j];
    }
    if (tid == 1023) g_bsum[blockIdx.x] = run;
}

// ---------------- scanB: scan of block totals ----------------
__global__ void k_scanB() {
    int lane = threadIdx.x;
    int v = (lane < SCAN_BLKS) ? g_bsum[lane] : 0;
    int x = v;
#pragma unroll
    for (int o = 1; o < 32; o <<= 1) {
        int t = __shfl_up_sync(0xffffffffu, x, o);
        if (lane >= o) x += t;
    }
    if (lane < SCAN_BLKS) g_bb[lane] = x - v;
}

// ---------------- CSR build ----------------
__global__ void __launch_bounds__(256) k_csr(const float* __restrict__ ew,
                                             const void* __restrict__ ei) {
    __shared__ int s64;
    if (threadIdx.x == 0) s64 = detect64(ei);
    __syncthreads();
    int is64 = s64;
    int e = blockIdx.x * 256 + threadIdx.x;
    if (e >= Ee) return;
    int r = ld_idx(ei, is64, e);
    int c = ld_idx(ei, is64, (long long)Ee + e);
    float nrm = g_dinv[r] * ew[e] * g_dinv[c];
    int p = g_off[c] + g_bb[c >> 12] + atomicAdd(&g_cur[c], 1);
    g_csr[p] = make_int2(r, __float_as_int(nrm));
}

// ---------------- agg1: warp/node CSR gather, fused bias+relu ----------------
__global__ void __launch_bounds__(256) k_agg1(const float* __restrict__ b1) {
    int n = (blockIdx.x * 256 + threadIdx.x) >> 5;
    if (n >= Nn) return;
    int lane = threadIdx.x & 31;
    int half = lane >> 4, q = lane & 15;
    int start = g_off[n] + g_bb[n >> 12];
    int end = start + g_cnt[n];
    const float4* xw4 = (const float4*)g_xw;

    float4 a = make_float4(0.f, 0.f, 0.f, 0.f);
    if (!half) {  // self-loop: dinv^2 * xw[n]
        float di = g_dinv[n];
        float w = di * di;
        float4 s = xw4[n * 16 + q];
        a = make_float4(w * s.x, w * s.y, w * s.z, w * s.w);
    }
    for (int e = start + half; e < end; e += 2) {
        int2 t = g_csr[e];
        float c = __int_as_float(t.y);
        float4 v = xw4[t.x * 16 + q];
        a.x += c * v.x; a.y += c * v.y; a.z += c * v.z; a.w += c * v.w;
    }
    a.x += __shfl_xor_sync(0xffffffffu, a.x, 16);
    a.y += __shfl_xor_sync(0xffffffffu, a.y, 16);
    a.z += __shfl_xor_sync(0xffffffffu, a.z, 16);
    a.w += __shfl_xor_sync(0xffffffffu, a.w, 16);
    if (!half) {
        float4 bb = *(const float4*)&b1[q * 4];
        ((float4*)g_h)[n * 16 + q] =
            make_float4(fmaxf(a.x + bb.x, 0.f), fmaxf(a.y + bb.y, 0.f),
                        fmaxf(a.z + bb.z, 0.f), fmaxf(a.w + bb.w, 0.f));
    }
}

// ---------------- GEMM2: g_hw = h @ W2 ----------------
__global__ void __launch_bounds__(320) k_gemm2(const float* __restrict__ W2) {
    __shared__ float w2s[64 * 40];
    __shared__ float hs[32 * 68];
    int tid = threadIdx.x;
    int row0 = blockIdx.x * 32;
    for (int i = tid; i < 64 * 40; i += 320) w2s[i] = W2[i];
    for (int i = tid; i < 32 * 64; i += 320)
        hs[(i >> 6) * 68 + (i & 63)] = g_h[row0 * 64 + i];
    __syncthreads();

    int rl = tid / 10, jq = tid - rl * 10;
    float4 acc = make_float4(0.f, 0.f, 0.f, 0.f);
#pragma unroll 8
    for (int k = 0; k < 64; k++) {
        float hv = hs[rl * 68 + k];
        float4 wv = *(const float4*)&w2s[k * 40 + jq * 4];
        acc.x += hv * wv.x;
        acc.y += hv * wv.y;
        acc.z += hv * wv.z;
        acc.w += hv * wv.w;
    }
    *(float4*)&g_hw[(row0 + rl) * Cc + jq * 4] = acc;
}

// ---------------- agg2: warp/node, fused bias + log_softmax ----------------
__global__ void __launch_bounds__(256) k_agg2(const float* __restrict__ b2,
                                              float* __restrict__ out, int mode) {
    int n = (blockIdx.x * 256 + threadIdx.x) >> 5;
    if (n >= Nn) return;
    int lane = threadIdx.x & 31;
    int half = lane >> 4, q = lane & 15;
    bool act = (q < 10);
    int start = g_off[n] + g_bb[n >> 12];
    int end = start + g_cnt[n];
    const float4* hw4 = (const float4*)g_hw;

    float4 a = make_float4(0.f, 0.f, 0.f, 0.f);
    if (!half && act) {
        float di = g_dinv[n];
        float w = di * di;
        float4 s = hw4[n * 10 + q];
        a = make_float4(w * s.x, w * s.y, w * s.z, w * s.w);
    }
    for (int e = start + half; e < end; e += 2) {
        int2 t = g_csr[e];
        float c = __int_as_float(t.y);
        if (act) {
            float4 v = hw4[t.x * 10 + q];
            a.x += c * v.x; a.y += c * v.y; a.z += c * v.z; a.w += c * v.w;
        }
    }
    a.x += __shfl_xor_sync(0xffffffffu, a.x, 16);
    a.y += __shfl_xor_sync(0xffffffffu, a.y, 16);
    a.z += __shfl_xor_sync(0xffffffffu, a.z, 16);
    a.w += __shfl_xor_sync(0xffffffffu, a.w, 16);

    float4 f = make_float4(0.f, 0.f, 0.f, 0.f);
    if (act) {
        float4 bb = *(const float4*)&b2[q * 4];
        f = make_float4(a.x + bb.x, a.y + bb.y, a.z + bb.z, a.w + bb.w);
    }
    float m = act ? fmaxf(fmaxf(f.x, f.y), fmaxf(f.z, f.w)) : -FLT_MAX;
#pragma unroll
    for (int o = 16; o; o >>= 1) m = fmaxf(m, __shfl_xor_sync(0xffffffffu, m, o));
    float s = 0.f;
    if (act && !half)
        s = __expf(f.x - m) + __expf(f.y - m) + __expf(f.z - m) + __expf(f.w - m);
#pragma unroll
    for (int o = 16; o; o >>= 1) s += __shfl_xor_sync(0xffffffffu, s, o);
    float lse = m + logf(s);

    if (act && !half) {
        float* fin = mode ? g_final : out;
        ((float4*)fin)[n * 10 + q] = f;
        float* L = mode ? out : out + Nn * Cc;
        ((float4*)L)[n * 10 + q] =
            make_float4(f.x - lse, f.y - lse, f.z - lse, f.w - lse);
    }
}

// ---------------- launcher ----------------
extern "C" void kernel_launch(void* const* d_in, const int* in_sizes, int n_in,
                              void* d_out, int out_size) {
    const float* x  = (const float*)d_in[0];
    const void*  ei = d_in[1];
    const float* ew = (const float*)d_in[2];
    const float* W1 = (const float*)d_in[3];
    const float* b1 = (const float*)d_in[4];
    const float* W2 = (const float*)d_in[5];
    const float* b2 = (const float*)d_in[6];
    float* out = (float*)d_out;

    int mode = (out_size >= 2 * Nn * Cc) ? 0 : 1;

    void* p_dc;  cudaGetSymbolAddress(&p_dc, g_dc);
    void* p_cur; cudaGetSymbolAddress(&p_cur, g_cur);
    cudaMemsetAsync(p_dc, 0, sizeof(float2) * Nn);
    cudaMemsetAsync(p_cur, 0, sizeof(int) * Nn);

    k_fused1<<<EBLK + GB1, 256>>>(x, W1, ew, ei);
    k_scanA<<<SCAN_BLKS, 1024>>>();
    k_scanB<<<1, 32>>>();
    k_csr<<<(Ee + 255) / 256, 256>>>(ew, ei);

    k_agg1<<<(Nn * 32 + 255) / 256, 256>>>(b1);
    k_gemm2<<<Nn / 32, 320>>>(W2);
    k_agg2<<<(Nn * 32 + 255) / 256, 256>>>(b2, out, mode);
}

// round 11
// speedup vs baseline: 1.0055x; 1.0055x over previous
#include <cuda_runtime.h>
#include <math.h>
#include <float.h>

#define Nn   100000
#define Ee   1600000
#define FIN  256
#define Hh   64
#define Cc   40

#define EBLK 296        // edge-processing blocks fused into K1
#define GB1  1563       // gemm1 blocks = ceil(Nn/64)
#define SCAN_BLKS 25    // 25 * 4096 >= Nn

// ---------------- scratch (device globals) ----------------
__device__ float2 g_dc[Nn];        // {sum(ew), count} accumulated atomically
__device__ float  g_dinv[Nn];
__device__ int    g_cnt[Nn];
__device__ int    g_off[Nn];       // block-local exclusive offsets
__device__ int    g_bsum[SCAN_BLKS];
__device__ int    g_bb[SCAN_BLKS]; // exclusive block bases
__device__ int    g_cur[Nn];       // scatter cursors (memset 0)
__device__ int2   g_csr[Ee];       // interleaved {src, norm_bits}
__device__ float  g_xw[Nn * Hh];
__device__ float  g_h[Nn * Hh];
__device__ float  g_hw[Nn * Cc];
__device__ float  g_final[Nn * Cc];

// ---------------- helpers ----------------
__device__ __forceinline__ unsigned long long dup2(float x) {
    unsigned long long r;
    asm("mov.b64 %0, {%1, %1};" : "=l"(r) : "f"(x));
    return r;
}
__device__ __forceinline__ void fma2(unsigned long long& d, unsigned long long a,
                                     unsigned long long b) {
    asm("fma.rn.f32x2 %0, %1, %2, %0;" : "+l"(d) : "l"(a), "l"(b));
}
__device__ __forceinline__ float2 unpk(unsigned long long v) {
    float2 f;
    asm("mov.b64 {%0, %1}, %2;" : "=f"(f.x), "=f"(f.y) : "l"(v));
    return f;
}
__device__ __forceinline__ void red_v2(float2* addr, float a, float b) {
    asm volatile("red.global.add.v2.f32 [%0], {%1, %2};"
                 :: "l"(addr), "f"(a), "f"(b) : "memory");
}
// per-block edge-index dtype detect: int64 node ids < 1e5 -> odd words all 0
__device__ __forceinline__ int detect64(const void* ei) {
    const unsigned int* u = (const unsigned int*)ei;
    int ok = 1;
#pragma unroll
    for (int k = 0; k < 64; k++)
        if (u[2 * k + 1] != 0u) ok = 0;
    return ok;
}
__device__ __forceinline__ int ld_idx(const void* ei, int is64, long long pos) {
    return is64 ? (int)((const long long*)ei)[pos] : ((const int*)ei)[pos];
}

// ---------------- K1: fused degcnt (edge blocks) + GEMM1 ----------------
__global__ void __launch_bounds__(256) k_fused1(const float* __restrict__ x,
                                                const float* __restrict__ W1,
                                                const float* __restrict__ ew,
                                                const void* __restrict__ ei) {
    __shared__ float xs[64 * 68];
    __shared__ float Ws[64 * 64];

    if (blockIdx.x < EBLK) {
        // -------- degree + count accumulation (grid-stride over edges) --------
        __shared__ int s64;
        if (threadIdx.x == 0) s64 = detect64(ei);
        __syncthreads();
        int is64 = s64;
        for (int e = blockIdx.x * 256 + threadIdx.x; e < Ee; e += EBLK * 256) {
            int c = ld_idx(ei, is64, (long long)Ee + e);
            red_v2(&g_dc[c], ew[e], 1.0f);
        }
        return;
    }

    // -------- GEMM1: g_xw = x @ W1 --------
    int tid = threadIdx.x;
    int tx = tid & 15, ty = tid >> 4;
    int row0 = (blockIdx.x - EBLK) * 64;

    unsigned long long acc[4][2] = {};

    for (int kt = 0; kt < 4; kt++) {
#pragma unroll
        for (int i = 0; i < 4; i++) {
            int lin = tid + i * 256;
            int r = lin >> 4, kq = lin & 15;
            float4 v = make_float4(0.f, 0.f, 0.f, 0.f);
            int rg = row0 + r;
            if (rg < Nn) v = *(const float4*)&x[rg * FIN + kt * 64 + kq * 4];
            *(float4*)&xs[r * 68 + kq * 4] = v;
        }
#pragma unroll
        for (int i = 0; i < 4; i++) {
            int lin = tid + i * 256;
            int k = lin >> 4, jq = lin & 15;
            *(float4*)&Ws[k * 64 + jq * 4] =
                *(const float4*)&W1[(kt * 64 + k) * Hh + jq * 4];
        }
        __syncthreads();

#pragma unroll 8
        for (int k = 0; k < 64; k++) {
            longlong2 wv = *(const longlong2*)&Ws[k * 64 + tx * 4];
            unsigned long long b0 = (unsigned long long)wv.x;
            unsigned long long b1 = (unsigned long long)wv.y;
#pragma unroll
            for (int i = 0; i < 4; i++) {
                unsigned long long a = dup2(xs[(ty * 4 + i) * 68 + k]);
                fma2(acc[i][0], a, b0);
                fma2(acc[i][1], a, b1);
            }
        }
        __syncthreads();
    }

#pragma unroll
    for (int i = 0; i < 4; i++) {
        int rg = row0 + ty * 4 + i;
        if (rg < Nn) {
            float2 lo = unpk(acc[i][0]);
            float2 hi = unpk(acc[i][1]);
            *(float4*)&g_xw[rg * Hh + tx * 4] = make_float4(lo.x, lo.y, hi.x, hi.y);
        }
    }
}

// ---------------- scanA: per-block local scan of counts, fused dinv ----------------
__global__ void __launch_bounds__(1024) k_scanA() {
    __shared__ int wsum[32];
    int tid = threadIdx.x, lane = tid & 31, wid = tid >> 5;
    int i0 = blockIdx.x * 4096 + tid * 4;

    int c[4];
    int s = 0;
#pragma unroll
    for (int j = 0; j < 4; j++) {
        int i = i0 + j;
        if (i < Nn) {
            float2 dc = g_dc[i];
            g_dinv[i] = rsqrtf(1.0f + dc.x);
            c[j] = (int)(dc.y + 0.5f);
            g_cnt[i] = c[j];
        } else c[j] = 0;
        s += c[j];
    }
    int x = s;
#pragma unroll
    for (int o = 1; o < 32; o <<= 1) {
        int t = __shfl_up_sync(0xffffffffu, x, o);
        if (lane >= o) x += t;
    }
    if (lane == 31) wsum[wid] = x;
    __syncthreads();
    if (wid == 0) {
        int y = wsum[lane];
#pragma unroll
        for (int o = 1; o < 32; o <<= 1) {
            int t = __shfl_up_sync(0xffffffffu, y, o);
            if (lane >= o) y += t;
        }
        wsum[lane] = y;
    }
    __syncthreads();
    int run = (x - s) + (wid ? wsum[wid - 1] : 0);  // exclusive
#pragma unroll
    for (int j = 0; j < 4; j++) {
        if (i0 + j < Nn) g_off[i0 + j] = run;
        run += c[j];
    }
    if (tid == 1023) g_bsum[blockIdx.x] = run;
}

// ---------------- scanB: scan of block totals ----------------
__global__ void k_scanB() {
    int lane = threadIdx.x;
    int v = (lane < SCAN_BLKS) ? g_bsum[lane] : 0;
    int x = v;
#pragma unroll
    for (int o = 1; o < 32; o <<= 1) {
        int t = __shfl_up_sync(0xffffffffu, x, o);
        if (lane >= o) x += t;
    }
    if (lane < SCAN_BLKS) g_bb[lane] = x - v;
}

// ---------------- CSR build ----------------
__global__ void __launch_bounds__(256) k_csr(const float* __restrict__ ew,
                                             const void* __restrict__ ei) {
    __shared__ int s64;
    if (threadIdx.x == 0) s64 = detect64(ei);
    __syncthreads();
    int is64 = s64;
    int e = blockIdx.x * 256 + threadIdx.x;
    if (e >= Ee) return;
    int r = ld_idx(ei, is64, e);
    int c = ld_idx(ei, is64, (long long)Ee + e);
    float nrm = g_dinv[r] * ew[e] * g_dinv[c];
    int p = g_off[c] + g_bb[c >> 12] + atomicAdd(&g_cur[c], 1);
    g_csr[p] = make_int2(r, __float_as_int(nrm));
}

// ---------------- agg1: warp/node CSR gather, fused bias+relu ----------------
__global__ void __launch_bounds__(256) k_agg1(const float* __restrict__ b1) {
    int n = (blockIdx.x * 256 + threadIdx.x) >> 5;
    if (n >= Nn) return;
    int lane = threadIdx.x & 31;
    int half = lane >> 4, q = lane & 15;
    int start = g_off[n] + g_bb[n >> 12];
    int end = start + g_cnt[n];
    const float4* xw4 = (const float4*)g_xw;

    float4 a = make_float4(0.f, 0.f, 0.f, 0.f);
    if (!half) {  // self-loop: dinv^2 * xw[n]
        float di = g_dinv[n];
        float w = di * di;
        float4 s = xw4[n * 16 + q];
        a = make_float4(w * s.x, w * s.y, w * s.z, w * s.w);
    }
    for (int e = start + half; e < end; e += 2) {
        int2 t = g_csr[e];
        float c = __int_as_float(t.y);
        float4 v = xw4[t.x * 16 + q];
        a.x += c * v.x; a.y += c * v.y; a.z += c * v.z; a.w += c * v.w;
    }
    a.x += __shfl_xor_sync(0xffffffffu, a.x, 16);
    a.y += __shfl_xor_sync(0xffffffffu, a.y, 16);
    a.z += __shfl_xor_sync(0xffffffffu, a.z, 16);
    a.w += __shfl_xor_sync(0xffffffffu, a.w, 16);
    if (!half) {
        float4 bb = *(const float4*)&b1[q * 4];
        ((float4*)g_h)[n * 16 + q] =
            make_float4(fmaxf(a.x + bb.x, 0.f), fmaxf(a.y + bb.y, 0.f),
                        fmaxf(a.z + bb.z, 0.f), fmaxf(a.w + bb.w, 0.f));
    }
}

// ---------------- GEMM2: g_hw = h @ W2 ----------------
__global__ void __launch_bounds__(320) k_gemm2(const float* __restrict__ W2) {
    __shared__ float w2s[64 * 40];
    __shared__ float hs[32 * 68];
    int tid = threadIdx.x;
    int row0 = blockIdx.x * 32;
    for (int i = tid; i < 64 * 40; i += 320) w2s[i] = W2[i];
    for (int i = tid; i < 32 * 64; i += 320)
        hs[(i >> 6) * 68 + (i & 63)] = g_h[row0 * 64 + i];
    __syncthreads();

    int rl = tid / 10, jq = tid - rl * 10;
    float4 acc = make_float4(0.f, 0.f, 0.f, 0.f);
#pragma unroll 8
    for (int k = 0; k < 64; k++) {
        float hv = hs[rl * 68 + k];
        float4 wv = *(const float4*)&w2s[k * 40 + jq * 4];
        acc.x += hv * wv.x;
        acc.y += hv * wv.y;
        acc.z += hv * wv.z;
        acc.w += hv * wv.w;
    }
    *(float4*)&g_hw[(row0 + rl) * Cc + jq * 4] = acc;
}

// ---------------- agg2: warp/node, fused bias + log_softmax ----------------
__global__ void __launch_bounds__(256) k_agg2(const float* __restrict__ b2,
                                              float* __restrict__ out, int mode) {
    int n = (blockIdx.x * 256 + threadIdx.x) >> 5;
    if (n >= Nn) return;
    int lane = threadIdx.x & 31;
    int half = lane >> 4, q = lane & 15;
    bool act = (q < 10);
    int start = g_off[n] + g_bb[n >> 12];
    int end = start + g_cnt[n];
    const float4* hw4 = (const float4*)g_hw;

    float4 a = make_float4(0.f, 0.f, 0.f, 0.f);
    if (!half && act) {
        float di = g_dinv[n];
        float w = di * di;
        float4 s = hw4[n * 10 + q];
        a = make_float4(w * s.x, w * s.y, w * s.z, w * s.w);
    }
    for (int e = start + half; e < end; e += 2) {
        int2 t = g_csr[e];
        float c = __int_as_float(t.y);
        if (act) {
            float4 v = hw4[t.x * 10 + q];
            a.x += c * v.x; a.y += c * v.y; a.z += c * v.z; a.w += c * v.w;
        }
    }
    a.x += __shfl_xor_sync(0xffffffffu, a.x, 16);
    a.y += __shfl_xor_sync(0xffffffffu, a.y, 16);
    a.z += __shfl_xor_sync(0xffffffffu, a.z, 16);
    a.w += __shfl_xor_sync(0xffffffffu, a.w, 16);

    float4 f = make_float4(0.f, 0.f, 0.f, 0.f);
    if (act) {
        float4 bb = *(const float4*)&b2[q * 4];
        f = make_float4(a.x + bb.x, a.y + bb.y, a.z + bb.z, a.w + bb.w);
    }
    float m = act ? fmaxf(fmaxf(f.x, f.y), fmaxf(f.z, f.w)) : -FLT_MAX;
#pragma unroll
    for (int o = 16; o; o >>= 1) m = fmaxf(m, __shfl_xor_sync(0xffffffffu, m, o));
    float s = 0.f;
    if (act && !half)
        s = __expf(f.x - m) + __expf(f.y - m) + __expf(f.z - m) + __expf(f.w - m);
#pragma unroll
    for (int o = 16; o; o >>= 1) s += __shfl_xor_sync(0xffffffffu, s, o);
    float lse = m + logf(s);

    if (act && !half) {
        float* fin = mode ? g_final : out;
        ((float4*)fin)[n * 10 + q] = f;
        float* L = mode ? out : out + Nn * Cc;
        ((float4*)L)[n * 10 + q] =
            make_float4(f.x - lse, f.y - lse, f.z - lse, f.w - lse);
    }
}

// ---------------- launcher ----------------
extern "C" void kernel_launch(void* const* d_in, const int* in_sizes, int n_in,
                              void* d_out, int out_size) {
    const float* x  = (const float*)d_in[0];
    const void*  ei = d_in[1];
    const float* ew = (const float*)d_in[2];
    const float* W1 = (const float*)d_in[3];
    const float* b1 = (const float*)d_in[4];
    const float* W2 = (const float*)d_in[5];
    const float* b2 = (const float*)d_in[6];
    float* out = (float*)d_out;

    int mode = (out_size >= 2 * Nn * Cc) ? 0 : 1;

    void* p_dc;  cudaGetSymbolAddress(&p_dc, g_dc);
    void* p_cur; cudaGetSymbolAddress(&p_cur, g_cur);
    cudaMemsetAsync(p_dc, 0, sizeof(float2) * Nn);
    cudaMemsetAsync(p_cur, 0, sizeof(int) * Nn);

    k_fused1<<<EBLK + GB1, 256>>>(x, W1, ew, ei);
    k_scanA<<<SCAN_BLKS, 1024>>>();
    k_scanB<<<1, 32>>>();
    k_csr<<<(Ee + 255) / 256, 256>>>(ew, ei);

    k_agg1<<<(Nn * 32 + 255) / 256, 256>>>(b1);
    k_gemm2<<<Nn / 32, 320>>>(W2);
    k_agg2<<<(Nn * 32 + 255) / 256, 256>>>(b2, out, mode);
}

// round 12
// speedup vs baseline: 1.0065x; 1.0010x over previous
#include <cuda_runtime.h>
#include <math.h>
#include <float.h>

#define Nn   100000
#define Ee   1600000
#define FIN  256
#define Hh   64
#define Cc   40

#define EBLK 296        // edge-processing blocks fused into K1
#define GB1  1563       // gemm1 blocks = ceil(Nn/64)
#define SCAN_BLKS 25    // 25 * 4096 >= Nn

// ---------------- scratch (device globals) ----------------
__device__ float2 g_dc[Nn];        // {sum(ew), count} accumulated atomically
__device__ float  g_dinv[Nn];
__device__ int    g_cnt[Nn];
__device__ int    g_off[Nn];       // block-local exclusive offsets
__device__ int    g_bsum[SCAN_BLKS];
__device__ int    g_bb[SCAN_BLKS]; // exclusive block bases
__device__ int    g_cur[Nn];       // scatter cursors (memset 0)
__device__ int2   g_csr[Ee];       // interleaved {src, norm_bits}
__device__ float  g_xw[Nn * Hh];
__device__ float  g_h[Nn * Hh];
__device__ float  g_hw[Nn * Cc];
__device__ float  g_final[Nn * Cc];

// ---------------- helpers ----------------
__device__ __forceinline__ unsigned long long dup2(float x) {
    unsigned long long r;
    asm("mov.b64 %0, {%1, %1};" : "=l"(r) : "f"(x));
    return r;
}
__device__ __forceinline__ void fma2(unsigned long long& d, unsigned long long a,
                                     unsigned long long b) {
    asm("fma.rn.f32x2 %0, %1, %2, %0;" : "+l"(d) : "l"(a), "l"(b));
}
__device__ __forceinline__ float2 unpk(unsigned long long v) {
    float2 f;
    asm("mov.b64 {%0, %1}, %2;" : "=f"(f.x), "=f"(f.y) : "l"(v));
    return f;
}
__device__ __forceinline__ void red_v2(float2* addr, float a, float b) {
    asm volatile("red.global.add.v2.f32 [%0], {%1, %2};"
                 :: "l"(addr), "f"(a), "f"(b) : "memory");
}
// per-block edge-index dtype detect: int64 node ids < 1e5 -> odd words all 0
__device__ __forceinline__ int detect64(const void* ei) {
    const unsigned int* u = (const unsigned int*)ei;
    int ok = 1;
#pragma unroll
    for (int k = 0; k < 64; k++)
        if (u[2 * k + 1] != 0u) ok = 0;
    return ok;
}
__device__ __forceinline__ int ld_idx(const void* ei, int is64, long long pos) {
    return is64 ? (int)((const long long*)ei)[pos] : ((const int*)ei)[pos];
}

// ---------------- K1: fused degcnt (edge blocks) + GEMM1 ----------------
__global__ void __launch_bounds__(256) k_fused1(const float* __restrict__ x,
                                                const float* __restrict__ W1,
                                                const float* __restrict__ ew,
                                                const void* __restrict__ ei) {
    __shared__ float xs[64 * 68];
    __shared__ float Ws[64 * 64];

    if (blockIdx.x < EBLK) {
        // -------- degree + count accumulation (grid-stride over edges) --------
        __shared__ int s64;
        if (threadIdx.x == 0) s64 = detect64(ei);
        __syncthreads();
        int is64 = s64;
        for (int e = blockIdx.x * 256 + threadIdx.x; e < Ee; e += EBLK * 256) {
            int c = ld_idx(ei, is64, (long long)Ee + e);
            red_v2(&g_dc[c], ew[e], 1.0f);
        }
        return;
    }

    // -------- GEMM1: g_xw = x @ W1 --------
    int tid = threadIdx.x;
    int tx = tid & 15, ty = tid >> 4;
    int row0 = (blockIdx.x - EBLK) * 64;

    unsigned long long acc[4][2] = {};

    for (int kt = 0; kt < 4; kt++) {
#pragma unroll
        for (int i = 0; i < 4; i++) {
            int lin = tid + i * 256;
            int r = lin >> 4, kq = lin & 15;
            float4 v = make_float4(0.f, 0.f, 0.f, 0.f);
            int rg = row0 + r;
            if (rg < Nn) v = *(const float4*)&x[rg * FIN + kt * 64 + kq * 4];
            *(float4*)&xs[r * 68 + kq * 4] = v;
        }
#pragma unroll
        for (int i = 0; i < 4; i++) {
            int lin = tid + i * 256;
            int k = lin >> 4, jq = lin & 15;
            *(float4*)&Ws[k * 64 + jq * 4] =
                *(const float4*)&W1[(kt * 64 + k) * Hh + jq * 4];
        }
        __syncthreads();

#pragma unroll 8
        for (int k = 0; k < 64; k++) {
            longlong2 wv = *(const longlong2*)&Ws[k * 64 + tx * 4];
            unsigned long long b0 = (unsigned long long)wv.x;
            unsigned long long b1 = (unsigned long long)wv.y;
#pragma unroll
            for (int i = 0; i < 4; i++) {
                unsigned long long a = dup2(xs[(ty * 4 + i) * 68 + k]);
                fma2(acc[i][0], a, b0);
                fma2(acc[i][1], a, b1);
            }
        }
        __syncthreads();
    }

#pragma unroll
    for (int i = 0; i < 4; i++) {
        int rg = row0 + ty * 4 + i;
        if (rg < Nn) {
            float2 lo = unpk(acc[i][0]);
            float2 hi = unpk(acc[i][1]);
            *(float4*)&g_xw[rg * Hh + tx * 4] = make_float4(lo.x, lo.y, hi.x, hi.y);
        }
    }
}

// ---------------- scanA: per-block local scan of counts, fused dinv ----------------
__global__ void __launch_bounds__(1024) k_scanA() {
    __shared__ int wsum[32];
    int tid = threadIdx.x, lane = tid & 31, wid = tid >> 5;
    int i0 = blockIdx.x * 4096 + tid * 4;

    int c[4];
    int s = 0;
#pragma unroll
    for (int j = 0; j < 4; j++) {
        int i = i0 + j;
        if (i < Nn) {
            float2 dc = g_dc[i];
            g_dinv[i] = rsqrtf(1.0f + dc.x);
            c[j] = (int)(dc.y + 0.5f);
            g_cnt[i] = c[j];
        } else c[j] = 0;
        s += c[j];
    }
    int x = s;
#pragma unroll
    for (int o = 1; o < 32; o <<= 1) {
        int t = __shfl_up_sync(0xffffffffu, x, o);
        if (lane >= o) x += t;
    }
    if (lane == 31) wsum[wid] = x;
    __syncthreads();
    if (wid == 0) {
        int y = wsum[lane];
#pragma unroll
        for (int o = 1; o < 32; o <<= 1) {
            int t = __shfl_up_sync(0xffffffffu, y, o);
            if (lane >= o) y += t;
        }
        wsum[lane] = y;
    }
    __syncthreads();
    int run = (x - s) + (wid ? wsum[wid - 1] : 0);  // exclusive
#pragma unroll
    for (int j = 0; j < 4; j++) {
        if (i0 + j < Nn) g_off[i0 + j] = run;
        run += c[j];
    }
    if (tid == 1023) g_bsum[blockIdx.x] = run;
}

// ---------------- scanB: scan of block totals ----------------
__global__ void k_scanB() {
    int lane = threadIdx.x;
    int v = (lane < SCAN_BLKS) ? g_bsum[lane] : 0;
    int x = v;
#pragma unroll
    for (int o = 1; o < 32; o <<= 1) {
        int t = __shfl_up_sync(0xffffffffu, x, o);
        if (lane >= o) x += t;
    }
    if (lane < SCAN_BLKS) g_bb[lane] = x - v;
}

// ---------------- CSR build ----------------
__global__ void __launch_bounds__(256) k_csr(const float* __restrict__ ew,
                                             const void* __restrict__ ei) {
    __shared__ int s64;
    if (threadIdx.x == 0) s64 = detect64(ei);
    __syncthreads();
    int is64 = s64;
    int e = blockIdx.x * 256 + threadIdx.x;
    if (e >= Ee) return;
    int r = ld_idx(ei, is64, e);
    int c = ld_idx(ei, is64, (long long)Ee + e);
    float nrm = g_dinv[r] * ew[e] * g_dinv[c];
    int p = g_off[c] + g_bb[c >> 12] + atomicAdd(&g_cur[c], 1);
    g_csr[p] = make_int2(r, __float_as_int(nrm));
}

// ---------------- agg1: warp/node CSR gather, fused bias+relu ----------------
__global__ void __launch_bounds__(256) k_agg1(const float* __restrict__ b1) {
    int n = (blockIdx.x * 256 + threadIdx.x) >> 5;
    if (n >= Nn) return;
    int lane = threadIdx.x & 31;
    int half = lane >> 4, q = lane & 15;
    int start = g_off[n] + g_bb[n >> 12];
    int end = start + g_cnt[n];
    const float4* xw4 = (const float4*)g_xw;

    float4 a = make_float4(0.f, 0.f, 0.f, 0.f);
    if (!half) {  // self-loop: dinv^2 * xw[n]
        float di = g_dinv[n];
        float w = di * di;
        float4 s = xw4[n * 16 + q];
        a = make_float4(w * s.x, w * s.y, w * s.z, w * s.w);
    }
    for (int e = start + half; e < end; e += 2) {
        int2 t = g_csr[e];
        float c = __int_as_float(t.y);
        float4 v = xw4[t.x * 16 + q];
        a.x += c * v.x; a.y += c * v.y; a.z += c * v.z; a.w += c * v.w;
    }
    a.x += __shfl_xor_sync(0xffffffffu, a.x, 16);
    a.y += __shfl_xor_sync(0xffffffffu, a.y, 16);
    a.z += __shfl_xor_sync(0xffffffffu, a.z, 16);
    a.w += __shfl_xor_sync(0xffffffffu, a.w, 16);
    if (!half) {
        float4 bb = *(const float4*)&b1[q * 4];
        ((float4*)g_h)[n * 16 + q] =
            make_float4(fmaxf(a.x + bb.x, 0.f), fmaxf(a.y + bb.y, 0.f),
                        fmaxf(a.z + bb.z, 0.f), fmaxf(a.w + bb.w, 0.f));
    }
}

// ---------------- GEMM2: g_hw = h @ W2 ----------------
__global__ void __launch_bounds__(320) k_gemm2(const float* __restrict__ W2) {
    __shared__ float w2s[64 * 40];
    __shared__ float hs[32 * 68];
    int tid = threadIdx.x;
    int row0 = blockIdx.x * 32;
    for (int i = tid; i < 64 * 40; i += 320) w2s[i] = W2[i];
    for (int i = tid; i < 32 * 64; i += 320)
        hs[(i >> 6) * 68 + (i & 63)] = g_h[row0 * 64 + i];
    __syncthreads();

    int rl = tid / 10, jq = tid - rl * 10;
    float4 acc = make_float4(0.f, 0.f, 0.f, 0.f);
#pragma unroll 8
    for (int k = 0; k < 64; k++) {
        float hv = hs[rl * 68 + k];
        float4 wv = *(const float4*)&w2s[k * 40 + jq * 4];
        acc.x += hv * wv.x;
        acc.y += hv * wv.y;
        acc.z += hv * wv.z;
        acc.w += hv * wv.w;
    }
    *(float4*)&g_hw[(row0 + rl) * Cc + jq * 4] = acc;
}

// ---------------- agg2: warp/node, fused bias + log_softmax ----------------
__global__ void __launch_bounds__(256) k_agg2(const float* __restrict__ b2,
                                              float* __restrict__ out, int mode) {
    int n = (blockIdx.x * 256 + threadIdx.x) >> 5;
    if (n >= Nn) return;
    int lane = threadIdx.x & 31;
    int half = lane >> 4, q = lane & 15;
    bool act = (q < 10);
    int start = g_off[n] + g_bb[n >> 12];
    int end = start + g_cnt[n];
    const float4* hw4 = (const float4*)g_hw;

    float4 a = make_float4(0.f, 0.f, 0.f, 0.f);
    if (!half && act) {
        float di = g_dinv[n];
        float w = di * di;
        float4 s = hw4[n * 10 + q];
        a = make_float4(w * s.x, w * s.y, w * s.z, w * s.w);
    }
    for (int e = start + half; e < end; e += 2) {
        int2 t = g_csr[e];
        float c = __int_as_float(t.y);
        if (act) {
            float4 v = hw4[t.x * 10 + q];
            a.x += c * v.x; a.y += c * v.y; a.z += c * v.z; a.w += c * v.w;
        }
    }
    a.x += __shfl_xor_sync(0xffffffffu, a.x, 16);
    a.y += __shfl_xor_sync(0xffffffffu, a.y, 16);
    a.z += __shfl_xor_sync(0xffffffffu, a.z, 16);
    a.w += __shfl_xor_sync(0xffffffffu, a.w, 16);

    float4 f = make_float4(0.f, 0.f, 0.f, 0.f);
    if (act) {
        float4 bb = *(const float4*)&b2[q * 4];
        f = make_float4(a.x + bb.x, a.y + bb.y, a.z + bb.z, a.w + bb.w);
    }
    float m = act ? fmaxf(fmaxf(f.x, f.y), fmaxf(f.z, f.w)) : -FLT_MAX;
#pragma unroll
    for (int o = 16; o; o >>= 1) m = fmaxf(m, __shfl_xor_sync(0xffffffffu, m, o));
    float s = 0.f;
    if (act && !half)
        s = __expf(f.x - m) + __expf(f.y - m) + __expf(f.z - m) + __expf(f.w - m);
#pragma unroll
    for (int o = 16; o; o >>= 1) s += __shfl_xor_sync(0xffffffffu, s, o);
    float lse = m + logf(s);

    if (act && !half) {
        float* fin = mode ? g_final : out;
        ((float4*)fin)[n * 10 + q] = f;
        float* L = mode ? out : out + Nn * Cc;
        ((float4*)L)[n * 10 + q] =
            make_float4(f.x - lse, f.y - lse, f.z - lse, f.w - lse);
    }
}

// ---------------- launcher ----------------
extern "C" void kernel_launch(void* const* d_in, const int* in_sizes, int n_in,
                              void* d_out, int out_size) {
    const float* x  = (const float*)d_in[0];
    const void*  ei = d_in[1];
    const float* ew = (const float*)d_in[2];
    const float* W1 = (const float*)d_in[3];
    const float* b1 = (const float*)d_in[4];
    const float* W2 = (const float*)d_in[5];
    const float* b2 = (const float*)d_in[6];
    float* out = (float*)d_out;

    int mode = (out_size >= 2 * Nn * Cc) ? 0 : 1;

    void* p_dc;  cudaGetSymbolAddress(&p_dc, g_dc);
    void* p_cur; cudaGetSymbolAddress(&p_cur, g_cur);
    cudaMemsetAsync(p_dc, 0, sizeof(float2) * Nn);
    cudaMemsetAsync(p_cur, 0, sizeof(int) * Nn);

    k_fused1<<<EBLK + GB1, 256>>>(x, W1, ew, ei);
    k_scanA<<<SCAN_BLKS, 1024>>>();
    k_scanB<<<1, 32>>>();
    k_csr<<<(Ee + 255) / 256, 256>>>(ew, ei);

    k_agg1<<<(Nn * 32 + 255) / 256, 256>>>(b1);
    k_gemm2<<<Nn / 32, 320>>>(W2);
    k_agg2<<<(Nn * 32 + 255) / 256, 256>>>(b2, out, mode);
}